// round 7
// baseline (speedup 1.0000x reference)
#include <cuda_runtime.h>
#include <math.h>

#define Uc 100
#define Vc 200
#define Nc 300
#define HDc 16
#define Hc 8
#define Bc 16
#define Ec 128
#define Lc 3
#define NEGC (-9000000000000000.0f)
#define ALPHAc 0.01f

// Scratch (allocation-free rule: __device__ globals)
__device__ float g_hE[Bc * Nc * Ec];            // post-GAT features, [B,300,128] flat
__device__ float g_p [Bc * Nc * Ec];            // pu rows 0..99, pv rows 100..299 per batch
__device__ unsigned char g_adj[Bc * Uc * Vc];   // canonical 0/1 adjacency
__device__ int g_mode4;                          // 0 = 1-byte bool, 1 = 4-byte (int32/float32)

// ---------------------------------------------------------------------------
// Dtype sniffer: bool bytes have nonzeros at byte offset i%4==1 (~30%);
// int32 0/1 only at i%4==0; float32 1.0f only at i%4 in {2,3}.
// Scans 32000 bytes (safe: adj buffer >= 320000 bytes in every candidate dtype).
// ---------------------------------------------------------------------------
__global__ void detect_adj(const unsigned char* __restrict__ adj)
{
    __shared__ int s_c1;
    if (threadIdx.x == 0) s_c1 = 0;
    __syncthreads();
    int c1 = 0;
    for (int i = threadIdx.x; i < 32000; i += 256)
        if ((i & 3) == 1 && adj[i]) c1++;
    if (c1) atomicAdd(&s_c1, c1);
    __syncthreads();
    if (threadIdx.x == 0) g_mode4 = (s_c1 == 0) ? 1 : 0;
}

// ---------------------------------------------------------------------------
// Stage A: 3 GAT layers, one CTA per (batch, head). Everything lives in smem.
// ---------------------------------------------------------------------------
#define SMEM_A ((4800 + 4800 + 20000 + 100 + 200 + 300 + 200 + 200 + 256 + 32) * 4 + 20000)

__global__ void __launch_bounds__(256, 1) gat_stage(
    const float* __restrict__ x, const unsigned char* __restrict__ adj,
    const float* __restrict__ Wl, const float* __restrict__ al)
{
    extern __shared__ float sm[];
    float* hs     = sm;
    float* Whs    = hs + 4800;
    float* attw   = Whs + 4800;
    float* eu     = attw + 20000;
    float* ev     = eu + 100;
    float* es     = ev + 200;
    float* rowinv = es + 300;
    float* selfe  = rowinv + 200;
    float* Wsm    = selfe + 200;
    float* av     = Wsm + 256;
    unsigned char* adjb = (unsigned char*)(av + 32);

    const int tid = threadIdx.x;
    const int warpId = tid >> 5, lane = tid & 31;
    const int b = blockIdx.x >> 3, head = blockIdx.x & 7;

    // head slice of x is CONTIGUOUS: flat reshape (B,H,N,hd)
    const float* xs = x + (size_t)(b * Hc + head) * (Nc * HDc);
    for (int i = tid; i < Nc * HDc; i += 256) hs[i] = xs[i];

    // normalized adjacency load (dtype-agnostic)
    if (g_mode4) {
        const unsigned int* ai = (const unsigned int*)adj + (size_t)b * Uc * Vc;
        for (int i = tid; i < Uc * Vc; i += 256) {
            unsigned char v = ai[i] ? 1 : 0;
            adjb[i] = v;
            if (head == 0) g_adj[(size_t)b * Uc * Vc + i] = v;
        }
    } else {
        const unsigned char* ab = adj + (size_t)b * Uc * Vc;
        for (int i = tid; i < Uc * Vc; i += 256) {
            unsigned char v = ab[i] ? 1 : 0;
            adjb[i] = v;
            if (head == 0) g_adj[(size_t)b * Uc * Vc + i] = v;
        }
    }
    __syncthreads();

    for (int lay = 0; lay < Lc; lay++) {
        const float* Wp = Wl + (size_t)(lay * Hc + head) * HDc * HDc;
        const float* ap = al + (size_t)(lay * Hc + head) * 2 * HDc;
        {   // W transposed into smem: Wsm[k*16+j] = W[j][k]
            int j = tid >> 4, k = tid & 15;
            Wsm[k * 16 + j] = Wp[j * 16 + k];
        }
        if (tid < 32) av[tid] = ap[tid];
        __syncthreads();

        // Wh[n][j] = sum_k h[n][k] * W[j][k]
        for (int i = tid; i < Nc * HDc; i += 256) {
            int n = i >> 4, j = i & 15;
            const float* hr = hs + (n << 4);
            float acc = 0.f;
#pragma unroll
            for (int k = 0; k < 16; k++) acc = fmaf(hr[k], Wsm[k * 16 + j], acc);
            Whs[i] = acc;
        }
        __syncthreads();

        // eu = Wh[:U].a1 ; ev = Wh[U:].a2 ; es = leaky(Wh.(a1+a2))
        for (int n = tid; n < Nc; n += 256) {
            const float4* wr = (const float4*)(Whs + n * 16);
            float d1 = 0.f, d2 = 0.f;
#pragma unroll
            for (int c = 0; c < 4; c++) {
                float4 q = wr[c];
                d1 = fmaf(q.x, av[4*c+0], d1); d2 = fmaf(q.x, av[16+4*c+0], d2);
                d1 = fmaf(q.y, av[4*c+1], d1); d2 = fmaf(q.y, av[16+4*c+1], d2);
                d1 = fmaf(q.z, av[4*c+2], d1); d2 = fmaf(q.z, av[16+4*c+2], d2);
                d1 = fmaf(q.w, av[4*c+3], d1); d2 = fmaf(q.w, av[16+4*c+3], d2);
            }
            if (n < Uc) eu[n] = d1; else ev[n - Uc] = d2;
            float s = d1 + d2;
            es[n] = fmaxf(s, ALPHAc * s);   // leaky_relu
        }
        __syncthreads();

        // ---- attU: softmax over v (200 edges + self), warp per u-row ----
        for (int u = warpId; u < Uc; u += 8) {
            const float base = eu[u];
            float m = -3.4e38f;
            for (int v = lane; v < Vc; v += 32) {
                float t = base + ev[v];
                float val = adjb[u * Vc + v] ? NEGC : fmaxf(t, ALPHAc * t);
                attw[u * Vc + v] = val;
                m = fmaxf(m, val);
            }
#pragma unroll
            for (int off = 16; off; off >>= 1) m = fmaxf(m, __shfl_xor_sync(0xffffffffu, m, off));
            const float se = es[u];
            m = fmaxf(m, se);
            float s = 0.f;
            for (int v = lane; v < Vc; v += 32) {
                float ex = __expf(attw[u * Vc + v] - m);
                attw[u * Vc + v] = ex;
                s += ex;
            }
#pragma unroll
            for (int off = 16; off; off >>= 1) s += __shfl_xor_sync(0xffffffffu, s, off);
            if (lane == 0) {
                float sx = __expf(se - m);
                rowinv[u] = 1.f / (s + sx);
                selfe[u]  = sx;
            }
        }
        __syncthreads();

        // hu -> hs[0..100)
        for (int i = tid; i < Uc * 4; i += 256) {
            int u = i >> 2, jq = i & 3;
            float se = selfe[u];
            float4 w0 = *((const float4*)(Whs + u * 16) + jq);
            float4 acc;
            acc.x = se * w0.x; acc.y = se * w0.y; acc.z = se * w0.z; acc.w = se * w0.w;
            const float* aw = attw + u * Vc;
            const float4* wv = (const float4*)(Whs + Uc * 16) + jq;
#pragma unroll 4
            for (int v = 0; v < Vc; v++) {
                float w = aw[v];
                float4 q = wv[v * 4];
                acc.x = fmaf(w, q.x, acc.x); acc.y = fmaf(w, q.y, acc.y);
                acc.z = fmaf(w, q.z, acc.z); acc.w = fmaf(w, q.w, acc.w);
            }
            float inv = rowinv[u];
            acc.x *= inv; acc.y *= inv; acc.z *= inv; acc.w *= inv;
            float4 r;
            r.x = acc.x > 0.f ? acc.x : expm1f(acc.x);
            r.y = acc.y > 0.f ? acc.y : expm1f(acc.y);
            r.z = acc.z > 0.f ? acc.z : expm1f(acc.z);
            r.w = acc.w > 0.f ? acc.w : expm1f(acc.w);
            *((float4*)(hs + u * 16) + jq) = r;
        }
        __syncthreads();

        // ---- attV: softmax over u (100 edges + self), warp per v-row ----
        for (int v = warpId; v < Vc; v += 8) {
            const float base = ev[v];
            float m = -3.4e38f;
            for (int u = lane; u < Uc; u += 32) {
                float t = eu[u] + base;
                float val = adjb[u * Vc + v] ? NEGC : fmaxf(t, ALPHAc * t);
                attw[v * Uc + u] = val;
                m = fmaxf(m, val);
            }
#pragma unroll
            for (int off = 16; off; off >>= 1) m = fmaxf(m, __shfl_xor_sync(0xffffffffu, m, off));
            const float se = es[Uc + v];
            m = fmaxf(m, se);
            float s = 0.f;
            for (int u = lane; u < Uc; u += 32) {
                float ex = __expf(attw[v * Uc + u] - m);
                attw[v * Uc + u] = ex;
                s += ex;
            }
#pragma unroll
            for (int off = 16; off; off >>= 1) s += __shfl_xor_sync(0xffffffffu, s, off);
            if (lane == 0) {
                float sx = __expf(se - m);
                rowinv[v] = 1.f / (s + sx);
                selfe[v]  = sx;
            }
        }
        __syncthreads();

        // hv -> hs[100..300)
        for (int i = tid; i < Vc * 4; i += 256) {
            int v = i >> 2, jq = i & 3;
            float se = selfe[v];
            float4 w0 = *((const float4*)(Whs + (Uc + v) * 16) + jq);
            float4 acc;
            acc.x = se * w0.x; acc.y = se * w0.y; acc.z = se * w0.z; acc.w = se * w0.w;
            const float* aw = attw + v * Uc;
            const float4* wu = (const float4*)Whs + jq;
#pragma unroll 4
            for (int u = 0; u < Uc; u++) {
                float w = aw[u];
                float4 q = wu[u * 4];
                acc.x = fmaf(w, q.x, acc.x); acc.y = fmaf(w, q.y, acc.y);
                acc.z = fmaf(w, q.z, acc.z); acc.w = fmaf(w, q.w, acc.w);
            }
            float inv = rowinv[v];
            acc.x *= inv; acc.y *= inv; acc.z *= inv; acc.w *= inv;
            float4 r;
            r.x = acc.x > 0.f ? acc.x : expm1f(acc.x);
            r.y = acc.y > 0.f ? acc.y : expm1f(acc.y);
            r.z = acc.z > 0.f ? acc.z : expm1f(acc.z);
            r.w = acc.w > 0.f ? acc.w : expm1f(acc.w);
            *((float4*)(hs + (Uc + v) * 16) + jq) = r;
        }
        __syncthreads();
    }

    // hE flat reshape back: head slice contiguous
    float* he = g_hE + (size_t)(b * Hc + head) * (Nc * HDc);
    for (int i = tid; i < Nc * HDc; i += 256) he[i] = hs[i];
}

// ---------------------------------------------------------------------------
// Stage B: p = hE @ W1^T (rows<100) / W2^T (rows>=100).
// ---------------------------------------------------------------------------
#define SMEM_B ((128 * 129 + 128 * 28) * 4)

__global__ void __launch_bounds__(128, 2) proj_stage(const float* __restrict__ Wlast)
{
    extern __shared__ float sm[];
    float* Wsm = sm;               // [o][e] padded stride 129
    float* hT  = sm + 128 * 129;   // [e][r] stride 28
    const int tid = threadIdx.x;
    const int b = blockIdx.x / 12, t = blockIdx.x % 12;
    const int row0 = (t < 4) ? t * 25 : Uc + (t - 4) * 25;
    const int woff = (t < 4) ? 0 : Ec;

    for (int idx = tid; idx < Ec * Ec; idx += 128) {
        int o = idx >> 7, e = idx & 127;
        Wsm[o * 129 + e] = Wlast[o * 257 + woff + e];
    }
    const float* hsrc = g_hE + (size_t)(b * Nc + row0) * Ec;
    for (int idx = tid; idx < 25 * Ec; idx += 128) {
        int r = idx >> 7, e = idx & 127;
        hT[e * 28 + r] = hsrc[r * Ec + e];
    }
    __syncthreads();

    float acc[25];
#pragma unroll
    for (int r = 0; r < 25; r++) acc[r] = 0.f;
    const float* wrow = Wsm + tid * 129;
#pragma unroll 4
    for (int e = 0; e < Ec; e++) {
        float w = wrow[e];
        const float* hp = hT + e * 28;
#pragma unroll
        for (int r = 0; r < 25; r++) acc[r] = fmaf(hp[r], w, acc[r]);
    }
    float* pd = g_p + (size_t)(b * Nc + row0) * Ec + tid;
#pragma unroll
    for (int r = 0; r < 25; r++) pd[r * Ec] = acc[r];
}

// ---------------------------------------------------------------------------
// Stage C: out[b,u,v,:] = (1-adj)*(pu+pv) + weights*wl.
// ---------------------------------------------------------------------------
__global__ void __launch_bounds__(256) final_stage(
    const float* __restrict__ wts, const float* __restrict__ Wlast,
    float* __restrict__ out)
{
    const int tid = threadIdx.x;
    const int warpId = tid >> 5, lane = tid & 31;
    const int b = blockIdx.x / 25;
    const int u0 = (blockIdx.x % 25) * 4;
    const int e0 = lane * 4;

    float4 wl4;
    wl4.x = Wlast[(e0 + 0) * 257 + 256];
    wl4.y = Wlast[(e0 + 1) * 257 + 256];
    wl4.z = Wlast[(e0 + 2) * 257 + 256];
    wl4.w = Wlast[(e0 + 3) * 257 + 256];

    float4 pu4[4];
#pragma unroll
    for (int i = 0; i < 4; i++)
        pu4[i] = *(const float4*)(g_p + (size_t)(b * Nc + u0 + i) * Ec + e0);

#pragma unroll 2
    for (int v = warpId; v < Vc; v += 8) {
        float4 pv4 = *(const float4*)(g_p + (size_t)(b * Nc + Uc + v) * Ec + e0);
#pragma unroll
        for (int i = 0; i < 4; i++) {
            const int u = u0 + i;
            const size_t base = (size_t)(b * Uc + u) * Vc + v;
            const float mf = g_adj[base] ? 0.f : 1.f;   // mask = 1 - adj
            const float wt = wts[base];
            float4 o4;
            o4.x = fmaf(wt, wl4.x, mf * (pu4[i].x + pv4.x));
            o4.y = fmaf(wt, wl4.y, mf * (pu4[i].y + pv4.y));
            o4.z = fmaf(wt, wl4.z, mf * (pu4[i].z + pv4.z));
            o4.w = fmaf(wt, wl4.w, mf * (pu4[i].w + pv4.w));
            *(float4*)(out + base * Ec + e0) = o4;
        }
    }
}

// ---------------------------------------------------------------------------
extern "C" void kernel_launch(void* const* d_in, const int* in_sizes, int n_in,
                              void* d_out, int out_size)
{
    const float*         x     = (const float*)d_in[0];
    const unsigned char* adj   = (const unsigned char*)d_in[1];  // dtype sniffed at runtime
    const float*         wts   = (const float*)d_in[2];
    const float*         Wl    = (const float*)d_in[3];
    const float*         al    = (const float*)d_in[4];
    const float*         Wlast = (const float*)d_in[5];
    float*               out   = (float*)d_out;

    cudaFuncSetAttribute(gat_stage,  cudaFuncAttributeMaxDynamicSharedMemorySize, SMEM_A);
    cudaFuncSetAttribute(proj_stage, cudaFuncAttributeMaxDynamicSharedMemorySize, SMEM_B);

    detect_adj<<<1, 256>>>(adj);
    gat_stage<<<Bc * Hc, 256, SMEM_A>>>(x, adj, Wl, al);
    proj_stage<<<Bc * 12, 128, SMEM_B>>>(Wlast);
    final_stage<<<Bc * 25, 256>>>(wts, Wlast, out);
}

// round 8
// speedup vs baseline: 1.3744x; 1.3744x over previous
#include <cuda_runtime.h>
#include <math.h>

#define Uc 100
#define Vc 200
#define Nc 300
#define HDc 16
#define Hc 8
#define Bc 16
#define Ec 128
#define Lc 3
#define NEGC (-9000000000000000.0f)
#define ALPHAc 0.01f

// Scratch (allocation-free rule: __device__ globals)
__device__ float g_hE[Bc * Nc * Ec];            // post-GAT features
__device__ float g_p [Bc * Nc * Ec];            // pu rows 0..99, pv rows 100..299 per batch
__device__ unsigned char g_adj[Bc * Uc * Vc];   // canonical 0/1 adjacency
__device__ int g_mode4;                          // 0 = 1-byte bool, 1 = 4-byte dtype

// ---------------------------------------------------------------------------
// Dtype sniffer: bool layout has nonzero bytes at offset 4i+1 (~30% density);
// int32/float32 0/1 have zero there. 2048 coalesced samples (8 KB span).
// ---------------------------------------------------------------------------
__global__ void detect_adj(const unsigned char* __restrict__ adj)
{
    __shared__ int s_c1;
    if (threadIdx.x == 0) s_c1 = 0;
    __syncthreads();
    int c1 = 0;
    for (int i = threadIdx.x; i < 2048; i += 256)
        if (adj[4 * i + 1]) c1++;
    if (c1) atomicAdd(&s_c1, c1);
    __syncthreads();
    if (threadIdx.x == 0) g_mode4 = (s_c1 == 0) ? 1 : 0;
}

// ---------------------------------------------------------------------------
// Stage A: 3 GAT layers, one 512-thread CTA per (batch, head).
// smem floats: hs 4800 | Whs 4800 | attw1 20000 | attw2 20000 | eu 100 | ev 200
//  | es 300 | rinvU 100 | selfU 100 | rinvV 200 | selfV 200 | Wsm 256 | av 32
//  | adjb 20000 bytes
// ---------------------------------------------------------------------------
#define SMEM_A ((4800 + 4800 + 20000 + 20000 + 100 + 200 + 300 + 100 + 100 + 200 + 200 + 256 + 32) * 4 + 20000)

__global__ void __launch_bounds__(512, 1) gat_stage(
    const float* __restrict__ x, const unsigned char* __restrict__ adj,
    const float* __restrict__ Wl, const float* __restrict__ al)
{
    extern __shared__ float sm[];
    float* hs    = sm;
    float* Whs   = hs + 4800;
    float* attw1 = Whs + 4800;      // [u][v] 100x200
    float* attw2 = attw1 + 20000;   // [v][u] 200x100
    float* eu    = attw2 + 20000;
    float* ev    = eu + 100;
    float* es    = ev + 200;
    float* rinvU = es + 300;
    float* selfU = rinvU + 100;
    float* rinvV = selfU + 100;
    float* selfV = rinvV + 200;
    float* Wsm   = selfV + 200;
    float* av    = Wsm + 256;
    unsigned char* adjb = (unsigned char*)(av + 32);

    const int tid = threadIdx.x;
    const int warpId = tid >> 5, lane = tid & 31;
    const int b = blockIdx.x >> 3, head = blockIdx.x & 7;

    // head slice of x is CONTIGUOUS: flat reshape (B,H,N,hd)
    const float* xs = x + (size_t)(b * Hc + head) * (Nc * HDc);
    for (int i = tid; i < Nc * HDc; i += 512) hs[i] = xs[i];

    // normalized adjacency load (dtype-agnostic)
    if (g_mode4) {
        const unsigned int* ai = (const unsigned int*)adj + (size_t)b * Uc * Vc;
        for (int i = tid; i < Uc * Vc; i += 512) {
            unsigned char v = ai[i] ? 1 : 0;
            adjb[i] = v;
            if (head == 0) g_adj[(size_t)b * Uc * Vc + i] = v;
        }
    } else {
        const unsigned char* ab = adj + (size_t)b * Uc * Vc;
        for (int i = tid; i < Uc * Vc; i += 512) {
            unsigned char v = ab[i] ? 1 : 0;
            adjb[i] = v;
            if (head == 0) g_adj[(size_t)b * Uc * Vc + i] = v;
        }
    }
    __syncthreads();

    for (int lay = 0; lay < Lc; lay++) {
        const float* Wp = Wl + (size_t)(lay * Hc + head) * HDc * HDc;
        const float* ap = al + (size_t)(lay * Hc + head) * 2 * HDc;
        if (tid < 256) {   // W transposed: Wsm[k*16+j] = W[j][k]
            int j = tid >> 4, k = tid & 15;
            Wsm[k * 16 + j] = Wp[j * 16 + k];
        }
        if (tid >= 256 && tid < 288) av[tid - 256] = ap[tid - 256];
        __syncthreads();

        // Wh[n][j] = sum_k h[n][k] * W[j][k]
        for (int i = tid; i < Nc * HDc; i += 512) {
            int n = i >> 4, j = i & 15;
            const float* hr = hs + (n << 4);
            float acc = 0.f;
#pragma unroll
            for (int k = 0; k < 16; k++) acc = fmaf(hr[k], Wsm[k * 16 + j], acc);
            Whs[i] = acc;
        }
        __syncthreads();

        // eu / ev / es
        for (int n = tid; n < Nc; n += 512) {
            const float4* wr = (const float4*)(Whs + n * 16);
            float d1 = 0.f, d2 = 0.f;
#pragma unroll
            for (int c = 0; c < 4; c++) {
                float4 q = wr[c];
                d1 = fmaf(q.x, av[4*c+0], d1); d2 = fmaf(q.x, av[16+4*c+0], d2);
                d1 = fmaf(q.y, av[4*c+1], d1); d2 = fmaf(q.y, av[16+4*c+1], d2);
                d1 = fmaf(q.z, av[4*c+2], d1); d2 = fmaf(q.z, av[16+4*c+2], d2);
                d1 = fmaf(q.w, av[4*c+3], d1); d2 = fmaf(q.w, av[16+4*c+3], d2);
            }
            if (n < Uc) eu[n] = d1; else ev[n - Uc] = d2;
            float s = d1 + d2;
            es[n] = fmaxf(s, ALPHAc * s);
        }
        __syncthreads();

        // ---- fused attU + attV softmaxes: warp per row, 300 rows, 16 warps ----
        for (int r = warpId; r < Nc; r += 16) {
            if (r < Uc) {
                const int u = r;
                const float base = eu[u];
                float m = -3.4e38f;
                for (int v = lane; v < Vc; v += 32) {
                    float t = base + ev[v];
                    float val = adjb[u * Vc + v] ? NEGC : fmaxf(t, ALPHAc * t);
                    attw1[u * Vc + v] = val;
                    m = fmaxf(m, val);
                }
#pragma unroll
                for (int off = 16; off; off >>= 1) m = fmaxf(m, __shfl_xor_sync(0xffffffffu, m, off));
                const float se = es[u];
                m = fmaxf(m, se);
                float s = 0.f;
                for (int v = lane; v < Vc; v += 32) {
                    float ex = __expf(attw1[u * Vc + v] - m);
                    attw1[u * Vc + v] = ex;
                    s += ex;
                }
#pragma unroll
                for (int off = 16; off; off >>= 1) s += __shfl_xor_sync(0xffffffffu, s, off);
                if (lane == 0) {
                    float sx = __expf(se - m);
                    rinvU[u] = 1.f / (s + sx);
                    selfU[u] = sx;
                }
            } else {
                const int v = r - Uc;
                const float base = ev[v];
                float m = -3.4e38f;
                for (int u = lane; u < Uc; u += 32) {
                    float t = eu[u] + base;
                    float val = adjb[u * Vc + v] ? NEGC : fmaxf(t, ALPHAc * t);
                    attw2[v * Uc + u] = val;
                    m = fmaxf(m, val);
                }
#pragma unroll
                for (int off = 16; off; off >>= 1) m = fmaxf(m, __shfl_xor_sync(0xffffffffu, m, off));
                const float se = es[Uc + v];
                m = fmaxf(m, se);
                float s = 0.f;
                for (int u = lane; u < Uc; u += 32) {
                    float ex = __expf(attw2[v * Uc + u] - m);
                    attw2[v * Uc + u] = ex;
                    s += ex;
                }
#pragma unroll
                for (int off = 16; off; off >>= 1) s += __shfl_xor_sync(0xffffffffu, s, off);
                if (lane == 0) {
                    float sx = __expf(se - m);
                    rinvV[v] = 1.f / (s + sx);
                    selfV[v] = sx;
                }
            }
        }
        __syncthreads();

        // ---- fused hu + hv aggregation: 1200 items over 512 threads ----
        for (int idx = tid; idx < 1200; idx += 512) {
            if (idx < 400) {
                int u = idx >> 2, jq = idx & 3;
                float se = selfU[u];
                float4 w0 = *((const float4*)(Whs + u * 16) + jq);
                float4 acc;
                acc.x = se * w0.x; acc.y = se * w0.y; acc.z = se * w0.z; acc.w = se * w0.w;
                const float* aw = attw1 + u * Vc;
                const float4* wv = (const float4*)(Whs + Uc * 16) + jq;
#pragma unroll 4
                for (int v = 0; v < Vc; v++) {
                    float w = aw[v];
                    float4 q = wv[v * 4];
                    acc.x = fmaf(w, q.x, acc.x); acc.y = fmaf(w, q.y, acc.y);
                    acc.z = fmaf(w, q.z, acc.z); acc.w = fmaf(w, q.w, acc.w);
                }
                float inv = rinvU[u];
                acc.x *= inv; acc.y *= inv; acc.z *= inv; acc.w *= inv;
                float4 r;
                r.x = acc.x > 0.f ? acc.x : expm1f(acc.x);
                r.y = acc.y > 0.f ? acc.y : expm1f(acc.y);
                r.z = acc.z > 0.f ? acc.z : expm1f(acc.z);
                r.w = acc.w > 0.f ? acc.w : expm1f(acc.w);
                *((float4*)(hs + u * 16) + jq) = r;
            } else {
                int t = idx - 400;
                int v = t >> 2, jq = t & 3;
                float se = selfV[v];
                float4 w0 = *((const float4*)(Whs + (Uc + v) * 16) + jq);
                float4 acc;
                acc.x = se * w0.x; acc.y = se * w0.y; acc.z = se * w0.z; acc.w = se * w0.w;
                const float* aw = attw2 + v * Uc;
                const float4* wu = (const float4*)Whs + jq;
#pragma unroll 4
                for (int u = 0; u < Uc; u++) {
                    float w = aw[u];
                    float4 q = wu[u * 4];
                    acc.x = fmaf(w, q.x, acc.x); acc.y = fmaf(w, q.y, acc.y);
                    acc.z = fmaf(w, q.z, acc.z); acc.w = fmaf(w, q.w, acc.w);
                }
                float inv = rinvV[v];
                acc.x *= inv; acc.y *= inv; acc.z *= inv; acc.w *= inv;
                float4 r;
                r.x = acc.x > 0.f ? acc.x : expm1f(acc.x);
                r.y = acc.y > 0.f ? acc.y : expm1f(acc.y);
                r.z = acc.z > 0.f ? acc.z : expm1f(acc.z);
                r.w = acc.w > 0.f ? acc.w : expm1f(acc.w);
                *((float4*)(hs + (Uc + v) * 16) + jq) = r;
            }
        }
        __syncthreads();
    }

    // hE flat reshape back: head slice contiguous
    float* he = g_hE + (size_t)(b * Hc + head) * (Nc * HDc);
    for (int i = tid; i < Nc * HDc; i += 512) he[i] = hs[i];
}

// ---------------------------------------------------------------------------
// Stage B: p = hE @ W1^T (rows<100) / W2^T (rows>=100).
// ---------------------------------------------------------------------------
#define SMEM_B ((128 * 129 + 128 * 28) * 4)

__global__ void __launch_bounds__(128, 2) proj_stage(const float* __restrict__ Wlast)
{
    extern __shared__ float sm[];
    float* Wsm = sm;               // [o][e] padded stride 129
    float* hT  = sm + 128 * 129;   // [e][r] stride 28
    const int tid = threadIdx.x;
    const int b = blockIdx.x / 12, t = blockIdx.x % 12;
    const int row0 = (t < 4) ? t * 25 : Uc + (t - 4) * 25;
    const int woff = (t < 4) ? 0 : Ec;

    for (int idx = tid; idx < Ec * Ec; idx += 128) {
        int o = idx >> 7, e = idx & 127;
        Wsm[o * 129 + e] = Wlast[o * 257 + woff + e];
    }
    const float* hsrc = g_hE + (size_t)(b * Nc + row0) * Ec;
    for (int idx = tid; idx < 25 * Ec; idx += 128) {
        int r = idx >> 7, e = idx & 127;
        hT[e * 28 + r] = hsrc[r * Ec + e];
    }
    __syncthreads();

    float acc[25];
#pragma unroll
    for (int r = 0; r < 25; r++) acc[r] = 0.f;
    const float* wrow = Wsm + tid * 129;
#pragma unroll 4
    for (int e = 0; e < Ec; e++) {
        float w = wrow[e];
        const float* hp = hT + e * 28;
#pragma unroll
        for (int r = 0; r < 25; r++) acc[r] = fmaf(hp[r], w, acc[r]);
    }
    float* pd = g_p + (size_t)(b * Nc + row0) * Ec + tid;
#pragma unroll
    for (int r = 0; r < 25; r++) pd[r * Ec] = acc[r];
}

// ---------------------------------------------------------------------------
// Stage C: out[b,u,v,:] = (1-adj)*(pu+pv) + weights*wl.  512 threads,
// streaming stores (output never re-read) keep g_p resident in L2.
// ---------------------------------------------------------------------------
__global__ void __launch_bounds__(512) final_stage(
    const float* __restrict__ wts, const float* __restrict__ Wlast,
    float* __restrict__ out)
{
    const int tid = threadIdx.x;
    const int warpId = tid >> 5, lane = tid & 31;
    const int b = blockIdx.x / 25;
    const int u0 = (blockIdx.x % 25) * 4;
    const int e0 = lane * 4;

    float4 wl4;
    wl4.x = Wlast[(e0 + 0) * 257 + 256];
    wl4.y = Wlast[(e0 + 1) * 257 + 256];
    wl4.z = Wlast[(e0 + 2) * 257 + 256];
    wl4.w = Wlast[(e0 + 3) * 257 + 256];

    float4 pu4[4];
#pragma unroll
    for (int i = 0; i < 4; i++)
        pu4[i] = *(const float4*)(g_p + (size_t)(b * Nc + u0 + i) * Ec + e0);

#pragma unroll 2
    for (int v = warpId; v < Vc; v += 16) {
        float4 pv4 = *(const float4*)(g_p + (size_t)(b * Nc + Uc + v) * Ec + e0);
#pragma unroll
        for (int i = 0; i < 4; i++) {
            const int u = u0 + i;
            const size_t base = (size_t)(b * Uc + u) * Vc + v;
            const float mf = g_adj[base] ? 0.f : 1.f;   // mask = 1 - adj
            const float wt = __ldcs(wts + base);
            float4 o4;
            o4.x = fmaf(wt, wl4.x, mf * (pu4[i].x + pv4.x));
            o4.y = fmaf(wt, wl4.y, mf * (pu4[i].y + pv4.y));
            o4.z = fmaf(wt, wl4.z, mf * (pu4[i].z + pv4.z));
            o4.w = fmaf(wt, wl4.w, mf * (pu4[i].w + pv4.w));
            __stcs((float4*)(out + base * Ec + e0), o4);
        }
    }
}

// ---------------------------------------------------------------------------
extern "C" void kernel_launch(void* const* d_in, const int* in_sizes, int n_in,
                              void* d_out, int out_size)
{
    const float*         x     = (const float*)d_in[0];
    const unsigned char* adj   = (const unsigned char*)d_in[1];  // dtype sniffed at runtime
    const float*         wts   = (const float*)d_in[2];
    const float*         Wl    = (const float*)d_in[3];
    const float*         al    = (const float*)d_in[4];
    const float*         Wlast = (const float*)d_in[5];
    float*               out   = (float*)d_out;

    cudaFuncSetAttribute(gat_stage,  cudaFuncAttributeMaxDynamicSharedMemorySize, SMEM_A);
    cudaFuncSetAttribute(proj_stage, cudaFuncAttributeMaxDynamicSharedMemorySize, SMEM_B);

    detect_adj<<<1, 256>>>(adj);
    gat_stage<<<Bc * Hc, 512, SMEM_A>>>(x, adj, Wl, al);
    proj_stage<<<Bc * 12, 128, SMEM_B>>>(Wlast);
    final_stage<<<Bc * 25, 512>>>(wts, Wlast, out);
}

// round 9
// speedup vs baseline: 1.4487x; 1.0540x over previous
#include <cuda_runtime.h>
#include <math.h>

#define Uc 100
#define Vc 200
#define Nc 300
#define HDc 16
#define Hc 8
#define Bc 16
#define Ec 128
#define Lc 3
#define NEGC (-9000000000000000.0f)
#define ALPHAc 0.01f

// Scratch (allocation-free rule: __device__ globals)
__device__ float g_hE[Bc * Nc * Ec];            // post-GAT features
__device__ float g_p [Bc * Nc * Ec];            // pu rows 0..99, pv rows 100..299 per batch
__device__ unsigned char g_adj[Bc * Uc * Vc];   // canonical 0/1 adjacency
__device__ int g_mode4;                          // 0 = 1-byte bool, 1 = 4-byte dtype

// ---------------------------------------------------------------------------
// Dtype sniffer: bool layout has nonzero bytes at offset 4i+1 (~30% density);
// int32/float32 0/1 have zero there.
// ---------------------------------------------------------------------------
__global__ void detect_adj(const unsigned char* __restrict__ adj)
{
    __shared__ int s_c1;
    if (threadIdx.x == 0) s_c1 = 0;
    __syncthreads();
    int c1 = 0;
    for (int i = threadIdx.x; i < 2048; i += 256)
        if (adj[4 * i + 1]) c1++;
    if (c1) atomicAdd(&s_c1, c1);
    __syncthreads();
    if (threadIdx.x == 0) g_mode4 = (s_c1 == 0) ? 1 : 0;
}

__device__ __forceinline__ float elu1(float v) { return v > 0.f ? v : expm1f(v); }

// ---------------------------------------------------------------------------
// Stage A: 3 GAT layers, one 512-thread CTA per (batch, head).
// ---------------------------------------------------------------------------
#define SMEM_A ((4800 + 4800 + 20000 + 20000 + 100 + 200 + 300 + 100 + 100 + 200 + 200 + 256 + 32) * 4 + 20000)

__global__ void __launch_bounds__(512, 1) gat_stage(
    const float* __restrict__ x, const unsigned char* __restrict__ adj,
    const float* __restrict__ Wl, const float* __restrict__ al)
{
    extern __shared__ float sm[];
    float* hs    = sm;
    float* Whs   = hs + 4800;
    float* attw1 = Whs + 4800;      // [u][v] 100x200 (exp values)
    float* attw2 = attw1 + 20000;   // [v][u] 200x100 (exp values)
    float* eu    = attw2 + 20000;
    float* ev    = eu + 100;
    float* es    = ev + 200;
    float* rinvU = es + 300;
    float* selfU = rinvU + 100;
    float* rinvV = selfU + 100;
    float* selfV = rinvV + 200;
    float* Wsm   = selfV + 200;
    float* av    = Wsm + 256;
    unsigned char* adjb = (unsigned char*)(av + 32);

    const int tid = threadIdx.x;
    const int warpId = tid >> 5, lane = tid & 31;
    const int b = blockIdx.x >> 3, head = blockIdx.x & 7;

    // head slice of x is CONTIGUOUS: flat reshape (B,H,N,hd)
    const float* xs = x + (size_t)(b * Hc + head) * (Nc * HDc);
    for (int i = tid; i < Nc * HDc; i += 512) hs[i] = xs[i];

    // normalized adjacency load (dtype-agnostic)
    if (g_mode4) {
        const unsigned int* ai = (const unsigned int*)adj + (size_t)b * Uc * Vc;
        for (int i = tid; i < Uc * Vc; i += 512) {
            unsigned char v = ai[i] ? 1 : 0;
            adjb[i] = v;
            if (head == 0) g_adj[(size_t)b * Uc * Vc + i] = v;
        }
    } else {
        const unsigned char* ab = adj + (size_t)b * Uc * Vc;
        for (int i = tid; i < Uc * Vc; i += 512) {
            unsigned char v = ab[i] ? 1 : 0;
            adjb[i] = v;
            if (head == 0) g_adj[(size_t)b * Uc * Vc + i] = v;
        }
    }
    __syncthreads();

    for (int lay = 0; lay < Lc; lay++) {
        const float* Wp = Wl + (size_t)(lay * Hc + head) * HDc * HDc;
        const float* ap = al + (size_t)(lay * Hc + head) * 2 * HDc;
        if (tid < 256) {   // W transposed: Wsm[k*16+j] = W[j][k]
            int j = tid >> 4, k = tid & 15;
            Wsm[k * 16 + j] = Wp[j * 16 + k];
        }
        if (tid >= 256 && tid < 288) av[tid - 256] = ap[tid - 256];
        __syncthreads();

        // Wh[n][j] = sum_k h[n][k] * W[j][k]
        for (int i = tid; i < Nc * HDc; i += 512) {
            int n = i >> 4, j = i & 15;
            const float* hr = hs + (n << 4);
            float acc = 0.f;
#pragma unroll
            for (int k = 0; k < 16; k++) acc = fmaf(hr[k], Wsm[k * 16 + j], acc);
            Whs[i] = acc;
        }
        __syncthreads();

        // eu / ev / es
        for (int n = tid; n < Nc; n += 512) {
            const float4* wr = (const float4*)(Whs + n * 16);
            float d1 = 0.f, d2 = 0.f;
#pragma unroll
            for (int c = 0; c < 4; c++) {
                float4 q = wr[c];
                d1 = fmaf(q.x, av[4*c+0], d1); d2 = fmaf(q.x, av[16+4*c+0], d2);
                d1 = fmaf(q.y, av[4*c+1], d1); d2 = fmaf(q.y, av[16+4*c+1], d2);
                d1 = fmaf(q.z, av[4*c+2], d1); d2 = fmaf(q.z, av[16+4*c+2], d2);
                d1 = fmaf(q.w, av[4*c+3], d1); d2 = fmaf(q.w, av[16+4*c+3], d2);
            }
            if (n < Uc) eu[n] = d1; else ev[n - Uc] = d2;
            float s = d1 + d2;
            es[n] = fmaxf(s, ALPHAc * s);
        }
        __syncthreads();

        // ---- fused attU/attV softmax: register-resident edge values ----
        for (int r = warpId; r < Nc; r += 16) {
            if (r < Uc) {
                const int u = r;
                const float base = eu[u];
                // 50 float4 groups: lane handles g0=lane and g1=lane+32 (if <50)
                float4 val0, val1;
                const int g1ok = (lane + 32) < 50;
                float m = -3.4e38f;
                {
                    const float4* ev4 = (const float4*)ev;
                    unsigned int msk = *(const unsigned int*)(adjb + u * Vc + lane * 4);
                    float4 e4 = ev4[lane];
                    float t;
                    t = base + e4.x; val0.x = (msk & 0x000000ffu) ? NEGC : fmaxf(t, ALPHAc * t);
                    t = base + e4.y; val0.y = (msk & 0x0000ff00u) ? NEGC : fmaxf(t, ALPHAc * t);
                    t = base + e4.z; val0.z = (msk & 0x00ff0000u) ? NEGC : fmaxf(t, ALPHAc * t);
                    t = base + e4.w; val0.w = (msk & 0xff000000u) ? NEGC : fmaxf(t, ALPHAc * t);
                    m = fmaxf(fmaxf(val0.x, val0.y), fmaxf(val0.z, val0.w));
                    if (g1ok) {
                        unsigned int msk1 = *(const unsigned int*)(adjb + u * Vc + (lane + 32) * 4);
                        float4 e41 = ev4[lane + 32];
                        t = base + e41.x; val1.x = (msk1 & 0x000000ffu) ? NEGC : fmaxf(t, ALPHAc * t);
                        t = base + e41.y; val1.y = (msk1 & 0x0000ff00u) ? NEGC : fmaxf(t, ALPHAc * t);
                        t = base + e41.z; val1.z = (msk1 & 0x00ff0000u) ? NEGC : fmaxf(t, ALPHAc * t);
                        t = base + e41.w; val1.w = (msk1 & 0xff000000u) ? NEGC : fmaxf(t, ALPHAc * t);
                        m = fmaxf(m, fmaxf(fmaxf(val1.x, val1.y), fmaxf(val1.z, val1.w)));
                    }
                }
#pragma unroll
                for (int off = 16; off; off >>= 1) m = fmaxf(m, __shfl_xor_sync(0xffffffffu, m, off));
                const float se = es[u];
                m = fmaxf(m, se);
                float s;
                {
                    float4 x0;
                    x0.x = __expf(val0.x - m); x0.y = __expf(val0.y - m);
                    x0.z = __expf(val0.z - m); x0.w = __expf(val0.w - m);
                    ((float4*)(attw1 + u * Vc))[lane] = x0;
                    s = (x0.x + x0.y) + (x0.z + x0.w);
                    if (g1ok) {
                        float4 x1;
                        x1.x = __expf(val1.x - m); x1.y = __expf(val1.y - m);
                        x1.z = __expf(val1.z - m); x1.w = __expf(val1.w - m);
                        ((float4*)(attw1 + u * Vc))[lane + 32] = x1;
                        s += (x1.x + x1.y) + (x1.z + x1.w);
                    }
                }
#pragma unroll
                for (int off = 16; off; off >>= 1) s += __shfl_xor_sync(0xffffffffu, s, off);
                if (lane == 0) {
                    float sx = __expf(se - m);
                    rinvU[u] = 1.f / (s + sx);
                    selfU[u] = sx;
                }
            } else {
                const int v = r - Uc;
                const float base = ev[v];
                // 25 float4 groups, lanes 0..24 active for data
                float4 val0;
                const int act = lane < 25;
                float m = -3.4e38f;
                if (act) {
                    const float4* eu4 = (const float4*)eu;
                    float4 e4 = eu4[lane];
                    // adjb strided by Vc per u
                    const unsigned char* ab = adjb + lane * 4 * Vc + v;
                    float t;
                    t = e4.x + base; val0.x = ab[0]        ? NEGC : fmaxf(t, ALPHAc * t);
                    t = e4.y + base; val0.y = ab[Vc]       ? NEGC : fmaxf(t, ALPHAc * t);
                    t = e4.z + base; val0.z = ab[2 * Vc]   ? NEGC : fmaxf(t, ALPHAc * t);
                    t = e4.w + base; val0.w = ab[3 * Vc]   ? NEGC : fmaxf(t, ALPHAc * t);
                    m = fmaxf(fmaxf(val0.x, val0.y), fmaxf(val0.z, val0.w));
                }
#pragma unroll
                for (int off = 16; off; off >>= 1) m = fmaxf(m, __shfl_xor_sync(0xffffffffu, m, off));
                const float se = es[Uc + v];
                m = fmaxf(m, se);
                float s = 0.f;
                if (act) {
                    float4 x0;
                    x0.x = __expf(val0.x - m); x0.y = __expf(val0.y - m);
                    x0.z = __expf(val0.z - m); x0.w = __expf(val0.w - m);
                    ((float4*)(attw2 + v * Uc))[lane] = x0;
                    s = (x0.x + x0.y) + (x0.z + x0.w);
                }
#pragma unroll
                for (int off = 16; off; off >>= 1) s += __shfl_xor_sync(0xffffffffu, s, off);
                if (lane == 0) {
                    float sx = __expf(se - m);
                    rinvV[v] = 1.f / (s + sx);
                    selfV[v] = sx;
                }
            }
        }
        __syncthreads();

        // ---- balanced 8-float aggregation ----
        // hu items: 200 (u,half), 200 inner iters each.  hv items: 400, 100 iters.
        // Schedule: tid<96 -> hv[tid], hv[304+tid]; 96<=tid<296 -> hu[tid-96];
        //           296<=tid (first 208) -> hv[96+tid-296].
        {
            int huItem = -1, hvA = -1, hvB = -1;
            if (tid < 96)            { hvA = tid; hvB = 304 + tid; }
            else if (tid < 296)      { huItem = tid - 96; }
            else if (tid - 296 < 208){ hvA = 96 + (tid - 296); }

            if (huItem >= 0) {
                const int u = huItem >> 1, half = huItem & 1;
                const float se = selfU[u];
                const float4* w0p = (const float4*)(Whs + u * 16) + half * 2;
                float4 a0, a1;
                float4 w00 = w0p[0], w01 = w0p[1];
                a0.x = se * w00.x; a0.y = se * w00.y; a0.z = se * w00.z; a0.w = se * w00.w;
                a1.x = se * w01.x; a1.y = se * w01.y; a1.z = se * w01.z; a1.w = se * w01.w;
                const float* aw = attw1 + u * Vc;
                const float4* wv = (const float4*)(Whs + Uc * 16) + half * 2;
#pragma unroll 4
                for (int v = 0; v < Vc; v++) {
                    float w = aw[v];
                    float4 q0 = wv[v * 4], q1 = wv[v * 4 + 1];
                    a0.x = fmaf(w, q0.x, a0.x); a0.y = fmaf(w, q0.y, a0.y);
                    a0.z = fmaf(w, q0.z, a0.z); a0.w = fmaf(w, q0.w, a0.w);
                    a1.x = fmaf(w, q1.x, a1.x); a1.y = fmaf(w, q1.y, a1.y);
                    a1.z = fmaf(w, q1.z, a1.z); a1.w = fmaf(w, q1.w, a1.w);
                }
                const float inv = rinvU[u];
                float4 r0, r1;
                r0.x = elu1(a0.x * inv); r0.y = elu1(a0.y * inv);
                r0.z = elu1(a0.z * inv); r0.w = elu1(a0.w * inv);
                r1.x = elu1(a1.x * inv); r1.y = elu1(a1.y * inv);
                r1.z = elu1(a1.z * inv); r1.w = elu1(a1.w * inv);
                float4* d = (float4*)(hs + u * 16) + half * 2;
                d[0] = r0; d[1] = r1;
            }
#pragma unroll
            for (int rep = 0; rep < 2; rep++) {
                int item = (rep == 0) ? hvA : hvB;
                if (item >= 0) {
                    const int v = item >> 1, half = item & 1;
                    const float se = selfV[v];
                    const float4* w0p = (const float4*)(Whs + (Uc + v) * 16) + half * 2;
                    float4 a0, a1;
                    float4 w00 = w0p[0], w01 = w0p[1];
                    a0.x = se * w00.x; a0.y = se * w00.y; a0.z = se * w00.z; a0.w = se * w00.w;
                    a1.x = se * w01.x; a1.y = se * w01.y; a1.z = se * w01.z; a1.w = se * w01.w;
                    const float* aw = attw2 + v * Uc;
                    const float4* wu = (const float4*)Whs + half * 2;
#pragma unroll 4
                    for (int u = 0; u < Uc; u++) {
                        float w = aw[u];
                        float4 q0 = wu[u * 4], q1 = wu[u * 4 + 1];
                        a0.x = fmaf(w, q0.x, a0.x); a0.y = fmaf(w, q0.y, a0.y);
                        a0.z = fmaf(w, q0.z, a0.z); a0.w = fmaf(w, q0.w, a0.w);
                        a1.x = fmaf(w, q1.x, a1.x); a1.y = fmaf(w, q1.y, a1.y);
                        a1.z = fmaf(w, q1.z, a1.z); a1.w = fmaf(w, q1.w, a1.w);
                    }
                    const float inv = rinvV[v];
                    float4 r0, r1;
                    r0.x = elu1(a0.x * inv); r0.y = elu1(a0.y * inv);
                    r0.z = elu1(a0.z * inv); r0.w = elu1(a0.w * inv);
                    r1.x = elu1(a1.x * inv); r1.y = elu1(a1.y * inv);
                    r1.z = elu1(a1.z * inv); r1.w = elu1(a1.w * inv);
                    float4* d = (float4*)(hs + (Uc + v) * 16) + half * 2;
                    d[0] = r0; d[1] = r1;
                }
            }
        }
        __syncthreads();
    }

    // hE flat reshape back: head slice contiguous
    float* he = g_hE + (size_t)(b * Hc + head) * (Nc * HDc);
    for (int i = tid; i < Nc * HDc; i += 512) he[i] = hs[i];
}

// ---------------------------------------------------------------------------
// Stage B: p = hE @ W1^T (rows<100) / W2^T (rows>=100).
// ---------------------------------------------------------------------------
#define SMEM_B ((128 * 129 + 128 * 28) * 4)

__global__ void __launch_bounds__(128, 2) proj_stage(const float* __restrict__ Wlast)
{
    extern __shared__ float sm[];
    float* Wsm = sm;               // [o][e] padded stride 129
    float* hT  = sm + 128 * 129;   // [e][r] stride 28
    const int tid = threadIdx.x;
    const int b = blockIdx.x / 12, t = blockIdx.x % 12;
    const int row0 = (t < 4) ? t * 25 : Uc + (t - 4) * 25;
    const int woff = (t < 4) ? 0 : Ec;

    for (int idx = tid; idx < Ec * Ec; idx += 128) {
        int o = idx >> 7, e = idx & 127;
        Wsm[o * 129 + e] = Wlast[o * 257 + woff + e];
    }
    const float* hsrc = g_hE + (size_t)(b * Nc + row0) * Ec;
    for (int idx = tid; idx < 25 * Ec; idx += 128) {
        int r = idx >> 7, e = idx & 127;
        hT[e * 28 + r] = hsrc[r * Ec + e];
    }
    __syncthreads();

    float acc[25];
#pragma unroll
    for (int r = 0; r < 25; r++) acc[r] = 0.f;
    const float* wrow = Wsm + tid * 129;
#pragma unroll 4
    for (int e = 0; e < Ec; e++) {
        float w = wrow[e];
        const float* hp = hT + e * 28;
#pragma unroll
        for (int r = 0; r < 25; r++) acc[r] = fmaf(hp[r], w, acc[r]);
    }
    float* pd = g_p + (size_t)(b * Nc + row0) * Ec + tid;
#pragma unroll
    for (int r = 0; r < 25; r++) pd[r * Ec] = acc[r];
}

// ---------------------------------------------------------------------------
// Stage C (R7 config): out[b,u,v,:] = (1-adj)*(pu+pv) + weights*wl.
// ---------------------------------------------------------------------------
__global__ void __launch_bounds__(256) final_stage(
    const float* __restrict__ wts, const float* __restrict__ Wlast,
    float* __restrict__ out)
{
    const int tid = threadIdx.x;
    const int warpId = tid >> 5, lane = tid & 31;
    const int b = blockIdx.x / 25;
    const int u0 = (blockIdx.x % 25) * 4;
    const int e0 = lane * 4;

    float4 wl4;
    wl4.x = Wlast[(e0 + 0) * 257 + 256];
    wl4.y = Wlast[(e0 + 1) * 257 + 256];
    wl4.z = Wlast[(e0 + 2) * 257 + 256];
    wl4.w = Wlast[(e0 + 3) * 257 + 256];

    float4 pu4[4];
#pragma unroll
    for (int i = 0; i < 4; i++)
        pu4[i] = *(const float4*)(g_p + (size_t)(b * Nc + u0 + i) * Ec + e0);

    for (int v = warpId; v < Vc; v += 8) {
        float4 pv4 = *(const float4*)(g_p + (size_t)(b * Nc + Uc + v) * Ec + e0);
#pragma unroll
        for (int i = 0; i < 4; i++) {
            const int u = u0 + i;
            const size_t base = (size_t)(b * Uc + u) * Vc + v;
            const float mf = g_adj[base] ? 0.f : 1.f;   // mask = 1 - adj
            const float wt = wts[base];
            float4 o4;
            o4.x = fmaf(wt, wl4.x, mf * (pu4[i].x + pv4.x));
            o4.y = fmaf(wt, wl4.y, mf * (pu4[i].y + pv4.y));
            o4.z = fmaf(wt, wl4.z, mf * (pu4[i].z + pv4.z));
            o4.w = fmaf(wt, wl4.w, mf * (pu4[i].w + pv4.w));
            *(float4*)(out + base * Ec + e0) = o4;
        }
    }
}

// ---------------------------------------------------------------------------
extern "C" void kernel_launch(void* const* d_in, const int* in_sizes, int n_in,
                              void* d_out, int out_size)
{
    const float*         x     = (const float*)d_in[0];
    const unsigned char* adj   = (const unsigned char*)d_in[1];  // dtype sniffed at runtime
    const float*         wts   = (const float*)d_in[2];
    const float*         Wl    = (const float*)d_in[3];
    const float*         al    = (const float*)d_in[4];
    const float*         Wlast = (const float*)d_in[5];
    float*               out   = (float*)d_out;

    cudaFuncSetAttribute(gat_stage,  cudaFuncAttributeMaxDynamicSharedMemorySize, SMEM_A);
    cudaFuncSetAttribute(proj_stage, cudaFuncAttributeMaxDynamicSharedMemorySize, SMEM_B);

    detect_adj<<<1, 256>>>(adj);
    gat_stage<<<Bc * Hc, 512, SMEM_A>>>(x, adj, Wl, al);
    proj_stage<<<Bc * 12, 128, SMEM_B>>>(Wlast);
    final_stage<<<Bc * 25, 256>>>(wts, Wlast, out);
}